// round 14
// baseline (speedup 1.0000x reference)
#include <cuda_runtime.h>
#include <cuda_bf16.h>
#include <cstdint>

#define T_  256
#define B_  64
#define E_  512
#define H_  512
#define KT  32      // num tags
#define G4  2048    // 4*H
#define NEGV -100000.0f

typedef __nv_bfloat16 bf16;

// ---------------- scratch (static device allocations are allowed) ----------------
__device__ __align__(16) bf16 g_x0b[(size_t)T_*B_*E_];    // embedded input bf16 [tb][512]
__device__ __align__(16) bf16 g_x1b[(size_t)T_*B_*2*H_];  // layer0 out bf16 [tb][1024]
__device__ __align__(16) bf16 g_x2b[(size_t)T_*B_*2*H_];  // layer1 out bf16 [tb][1024]
__device__ __align__(16) bf16 g_wih0b[(size_t)2*G4*E_];   // wih0 bf16
__device__ __align__(16) bf16 g_wih1b[(size_t)2*G4*2*H_]; // wih1 bf16
__device__ float g_xp[(size_t)2*T_*G4*B_];        // input-proj gates fp32 [d][t][g][b]
__device__ __align__(16) bf16 g_hbb[(size_t)2*2*B_*H_];  // h bf16, ping-pong: [par][d][b][k]
__device__ float g_feats[(size_t)T_*B_*KT];       // emission scores
__device__ float g_part[B_];
__device__ __align__(256) unsigned g_flag[2][64]; // per-block arrival flags (monotonic)

// ---------------- helpers ----------------
__device__ __forceinline__ void mma_bf(float* c, uint32_t a0, uint32_t a1,
                                       uint32_t a2, uint32_t a3,
                                       uint32_t b0, uint32_t b1)
{
    asm volatile(
        "mma.sync.aligned.m16n8k16.row.col.f32.bf16.bf16.f32 "
        "{%0,%1,%2,%3},{%4,%5,%6,%7},{%8,%9},{%0,%1,%2,%3};"
        : "+f"(c[0]), "+f"(c[1]), "+f"(c[2]), "+f"(c[3])
        : "r"(a0), "r"(a1), "r"(a2), "r"(a3), "r"(b0), "r"(b1));
}

__device__ __forceinline__ float sigf(float x) {
    return 1.f / (1.f + __expf(-x));
}

// grid barrier among the 64 blocks of one direction. ZERO atomics, NO leader:
// arrival = plain store of a monotonic generation to the block's own flag slot;
// EVERY block polls all 64 flags itself (64 threads, 2 coalesced lines) —
// removes the leader publish+detect hop (one L2 round trip) from the chain.
__device__ __forceinline__ void gbarrier(int d, int bid, unsigned gen) {
    __syncthreads();
    if (threadIdx.x == 0) {
        __threadfence();                              // release: h stores visible first
        *((volatile unsigned*)&g_flag[d][bid]) = gen;
    }
    if (threadIdx.x < 64) {
        while (*((volatile unsigned*)&g_flag[d][threadIdx.x]) < gen) { __nanosleep(8); }
    }
    __syncthreads();
    if (threadIdx.x == 0) __threadfence();            // acquire: flush L1D before h reads
    __syncthreads();
}

// ---------------- weight conversion fp32 -> bf16 (wih only) ----------------
__global__ void cvt_k(const float* __restrict__ wih0, const float* __restrict__ wih1) {
    int i = blockIdx.x * 256 + threadIdx.x;   // float4 index
    const float* s; bf16* dst; int off;
    if (i < 524288)       { s = wih0; dst = g_wih0b; off = i; }
    else if (i < 1572864) { s = wih1; dst = g_wih1b; off = i - 524288; }
    else return;
    float4 v = ((const float4*)s)[off];
    __nv_bfloat162* o = (__nv_bfloat162*)dst + (size_t)off * 2;
    o[0] = __floats2bfloat162_rn(v.x, v.y);
    o[1] = __floats2bfloat162_rn(v.z, v.w);
}

// ---------------- embedding lookup -> bf16 ----------------
__global__ void embed_k(const int* __restrict__ tokens, const float* __restrict__ embed) {
    size_t i = (size_t)blockIdx.x * blockDim.x + threadIdx.x;   // float4 index
    if (i >= (size_t)T_ * B_ * E_ / 4) return;
    size_t el = i * 4;
    size_t tb = el / E_;
    int    e  = (int)(el % E_);
    const float4 v = *(const float4*)(embed + (size_t)tokens[tb] * E_ + e);
    __nv_bfloat162* o = (__nv_bfloat162*)(g_x0b + el);
    o[0] = __floats2bfloat162_rn(v.x, v.y);
    o[1] = __floats2bfloat162_rn(v.z, v.w);
}

// ---------------- input projection GEMM: 2 timesteps per block (N=128) ----------
// W tile re-read halved vs round 11. X rows for (t0, t0+1) are contiguous, so
// Bs staging is one coalesced 128-row copy. Register prefetch kept.
template<int L>
__global__ __launch_bounds__(256) void gemm_xp_k(const float* __restrict__ bias)
{
    constexpr int KSZ = (L == 0) ? 512 : 1024;
    const bf16* X = (L == 0) ? g_x0b : g_x1b;
    const bf16* Wb = (L == 0) ? g_wih0b : g_wih1b;

    __shared__ __align__(16) bf16 As[128][40];
    __shared__ __align__(16) bf16 Bs[128][40];   // two 64-row timestep tiles

    const int d = blockIdx.z, t0 = blockIdx.y * 2, gbase = blockIdx.x * 128;
    const bf16* Wd = Wb + (size_t)d * G4 * KSZ;
    const bf16* Xt = X + (size_t)t0 * B_ * KSZ;   // 128 contiguous tb rows

    const int tid = threadIdx.x, warp = tid >> 5, lane = tid & 31;
    const int wm = (warp >> 1) * 32, wn = (warp & 1) * 32;
    const int gid = lane >> 2, tig = lane & 3;

    float acc[2][2][4][4];    // [tt][mt][nt][4]
#pragma unroll
    for (int a = 0; a < 2; a++)
#pragma unroll
        for (int b = 0; b < 2; b++)
#pragma unroll
            for (int c = 0; c < 4; c++)
#pragma unroll
                for (int e = 0; e < 4; e++) acc[a][b][c][e] = 0.f;

    const int row0 = tid >> 2;          // 0..63
    const int c8   = (tid & 3) * 8;

    uint4 ra0, ra1, rb0, rb1;
    auto LD = [&](int k0) {
        ra0 = *(const uint4*)(Wd + (size_t)(gbase + row0) * KSZ + k0 + c8);
        ra1 = *(const uint4*)(Wd + (size_t)(gbase + row0 + 64) * KSZ + k0 + c8);
        rb0 = *(const uint4*)(Xt + (size_t)row0 * KSZ + k0 + c8);
        rb1 = *(const uint4*)(Xt + (size_t)(row0 + 64) * KSZ + k0 + c8);
    };
    LD(0);

    for (int k0 = 0; k0 < KSZ; k0 += 32) {
        *(uint4*)&As[row0][c8]      = ra0;
        *(uint4*)&As[row0 + 64][c8] = ra1;
        *(uint4*)&Bs[row0][c8]      = rb0;
        *(uint4*)&Bs[row0 + 64][c8] = rb1;
        __syncthreads();
        if (k0 + 32 < KSZ) LD(k0 + 32);     // prefetch next chunk (hides under mma)
#pragma unroll
        for (int ks = 0; ks < 2; ks++) {
            const int kk = ks * 16 + 2 * tig;
            uint32_t a[2][4];
#pragma unroll
            for (int mt = 0; mt < 2; mt++) {
                int r0 = wm + mt * 16 + gid;
                a[mt][0] = *(const uint32_t*)&As[r0][kk];
                a[mt][1] = *(const uint32_t*)&As[r0 + 8][kk];
                a[mt][2] = *(const uint32_t*)&As[r0][kk + 8];
                a[mt][3] = *(const uint32_t*)&As[r0 + 8][kk + 8];
            }
#pragma unroll
            for (int tt = 0; tt < 2; tt++) {
#pragma unroll
                for (int nt = 0; nt < 4; nt++) {
                    int ci = tt * 64 + wn + nt * 8 + gid;
                    uint32_t b0 = *(const uint32_t*)&Bs[ci][kk];
                    uint32_t b1 = *(const uint32_t*)&Bs[ci][kk + 8];
                    mma_bf(acc[tt][0][nt], a[0][0], a[0][1], a[0][2], a[0][3], b0, b1);
                    mma_bf(acc[tt][1][nt], a[1][0], a[1][1], a[1][2], a[1][3], b0, b1);
                }
            }
        }
        __syncthreads();
    }
#pragma unroll
    for (int tt = 0; tt < 2; tt++) {
        float* XP = g_xp + ((size_t)(d * T_ + t0 + tt) * G4) * B_;
#pragma unroll
        for (int mt = 0; mt < 2; mt++) {
            int r0 = gbase + wm + mt * 16 + gid;
            float bb0 = bias[(size_t)d * G4 + r0];
            float bb1 = bias[(size_t)d * G4 + r0 + 8];
#pragma unroll
            for (int nt = 0; nt < 4; nt++) {
                int c = wn + nt * 8 + tig * 2;
                float2 v0 = make_float2(acc[tt][mt][nt][0] + bb0, acc[tt][mt][nt][1] + bb0);
                float2 v1 = make_float2(acc[tt][mt][nt][2] + bb1, acc[tt][mt][nt][3] + bb1);
                *(float2*)(XP + (size_t)r0 * B_ + c)       = v0;
                *(float2*)(XP + (size_t)(r0 + 8) * B_ + c) = v1;
            }
        }
    }
}

// ---------------- recurrence kernel (round-12 structure, leaderless barrier) -----
// smem: whh 32x520 bf16 + h 64x520 bf16 + z 32x68 f32 = 108544 B
#define REC_SMEM ((32 * 520 + 64 * 520) * 2 + 32 * 68 * 4)

template<int L>
__global__ __launch_bounds__(256, 1) void lstm_rec_k(const float* __restrict__ Whh)
{
    bf16* Xout = (L == 0) ? g_x1b : g_x2b;
    extern __shared__ char smraw[];
    bf16*  whh_s = (bf16*)smraw;                     // [32][520]
    bf16*  h_s   = (bf16*)(smraw + 32 * 520 * 2);    // [64][520]
    float* z_s   = (float*)(smraw + (32 + 64) * 520 * 2); // [32][68]

    const int blk = blockIdx.x;
    const int d = blk >> 6;
    const int bid = blk & 63;
    const int jbase = bid * 8;
    const int tid = threadIdx.x, warp = tid >> 5, lane = tid & 31;
    const int gid = lane >> 2, tig = lane & 3;
    const int wm = (warp >> 2) * 16, wn = (warp & 3) * 16;

    // monotonic generation base: this block's OWN flag (self-written -> stable,
    // and equal across blocks since all execute the same number of barriers)
    __shared__ unsigned s_base;
    if (tid == 0) s_base = *((volatile unsigned*)&g_flag[d][bid]);

    const float* Wd = Whh + (size_t)d * G4 * H_;

    // load + convert this block's 32 Whh rows (local m = q*8+jl <-> q*512+jbase+jl)
    for (int i = tid; i < 32 * 128; i += 256) {
        int m = i >> 7, c4 = (i & 127) * 4;
        int grow = (m >> 3) * 512 + jbase + (m & 7);
        float4 v = *(const float4*)(Wd + (size_t)grow * H_ + c4);
        __nv_bfloat162 p0 = __floats2bfloat162_rn(v.x, v.y);
        __nv_bfloat162 p1 = __floats2bfloat162_rn(v.z, v.w);
        uint2 pk = make_uint2(*(uint32_t*)&p0, *(uint32_t*)&p1);
        *(uint2*)&whh_s[m * 520 + c4] = pk;
    }

    // per-thread cells: b = tid>>2 (0..63), j0 = (tid&3)*2
    const int b  = tid >> 2;
    const int j0 = (tid & 3) * 2;
    float cst[2] = {0.f, 0.f};

    // zero h_{-1} into parity buffer 0
    *(__nv_bfloat162*)(g_hbb + ((size_t)(0 * 2 + d) * B_ + b) * H_ + jbase + j0) =
        __floats2bfloat162_rn(0.f, 0.f);

    __syncthreads();
    unsigned gen = s_base + 1;

    gbarrier(d, bid, gen); gen++;

    for (int s = 0; s < T_; s++) {
        const int t = (d == 0) ? s : (T_ - 1 - s);
        const int rb = s & 1;          // read parity
        const int wb = rb ^ 1;         // write parity
        const bf16* hsrc = g_hbb + (size_t)(rb * 2 + d) * B_ * H_;

        // hoisted xp gate loads (8 independent fp32; hide under staging + mma)
        const float* xpb = g_xp + ((size_t)(d * T_ + t) * G4 + jbase) * B_;
        float xv[4][2];
#pragma unroll
        for (int q = 0; q < 4; q++)
#pragma unroll
            for (int u = 0; u < 2; u++)
                xv[q][u] = xpb[(size_t)(q * 512 + j0 + u) * B_ + b];

        // stage FULL h (64 x 512 bf16) once: 16 uint4 per thread
#pragma unroll
        for (int p = 0; p < 16; p++) {
            int idx = p * 256 + tid;
            int row = idx >> 6;
            int c8  = (idx & 63) * 8;
            *(uint4*)&h_s[row * 520 + c8] = *(const uint4*)(hsrc + (size_t)row * H_ + c8);
        }
        __syncthreads();

        float z[2][4] = {{0.f,0.f,0.f,0.f},{0.f,0.f,0.f,0.f}};
#pragma unroll 8
        for (int ks = 0; ks < 32; ks++) {
            const int kk = ks * 16 + 2 * tig;
            const int ar = wm + gid;
            uint32_t a0 = *(const uint32_t*)&whh_s[ar * 520 + kk];
            uint32_t a1 = *(const uint32_t*)&whh_s[(ar + 8) * 520 + kk];
            uint32_t a2 = *(const uint32_t*)&whh_s[ar * 520 + kk + 8];
            uint32_t a3 = *(const uint32_t*)&whh_s[(ar + 8) * 520 + kk + 8];
#pragma unroll
            for (int nt = 0; nt < 2; nt++) {
                int nc = wn + nt * 8 + gid;
                uint32_t b0 = *(const uint32_t*)&h_s[nc * 520 + kk];
                uint32_t b1 = *(const uint32_t*)&h_s[nc * 520 + kk + 8];
                mma_bf(z[nt], a0, a1, a2, a3, b0, b1);
            }
        }

        // z fragments -> smem
#pragma unroll
        for (int nt = 0; nt < 2; nt++) {
            int cc = wn + nt * 8 + tig * 2;
            *(float2*)&z_s[(wm + gid) * 68 + cc]     = make_float2(z[nt][0], z[nt][1]);
            *(float2*)&z_s[(wm + gid + 8) * 68 + cc] = make_float2(z[nt][2], z[nt][3]);
        }
        __syncthreads();

        // gates + state update for cells (jbase+j0, b), (jbase+j0+1, b)
        float hv[2];
#pragma unroll
        for (int u = 0; u < 2; u++) {
            int j = j0 + u;
            float zi = z_s[(j)      * 68 + b] + xv[0][u];
            float zf = z_s[(8 + j)  * 68 + b] + xv[1][u];
            float zg = z_s[(16 + j) * 68 + b] + xv[2][u];
            float zo = z_s[(24 + j) * 68 + b] + xv[3][u];
            float iv = sigf(zi), fv = sigf(zf), ov = sigf(zo);
            float gv = tanhf(zg);
            cst[u] = fv * cst[u] + iv * gv;
            hv[u] = ov * tanhf(cst[u]);
        }
        __nv_bfloat162 hb = __floats2bfloat162_rn(hv[0], hv[1]);
        *(__nv_bfloat162*)(g_hbb + ((size_t)(wb * 2 + d) * B_ + b) * H_ + jbase + j0) = hb;
        *(__nv_bfloat162*)(Xout + ((size_t)t * B_ + b) * (2 * H_) + d * H_ + jbase + j0) = hb;

        gbarrier(d, bid, gen); gen++;
    }
}

// ---------------- emission scores (round-8 verbatim) ----------------
__global__ __launch_bounds__(256) void feats_k(const float* __restrict__ lw,
                                               const float* __restrict__ lb)
{
    __shared__ float xs[8][129];
    __shared__ float ws[32][129];
    const int tid = threadIdx.x;
    const int r = tid >> 5, k = tid & 31;
    const size_t tb0 = (size_t)blockIdx.x * 8;
    float acc = 0.f;
    for (int c0 = 0; c0 < 2 * H_; c0 += 128) {
        for (int i = tid; i < 8 * 128; i += 256)
            xs[i >> 7][i & 127] =
                __bfloat162float(g_x2b[(tb0 + (i >> 7)) * (2 * H_) + c0 + (i & 127)]);
        for (int i = tid; i < 32 * 128; i += 256)
            ws[i >> 7][i & 127] = lw[(size_t)(i >> 7) * (2 * H_) + c0 + (i & 127)];
        __syncthreads();
#pragma unroll 16
        for (int kk = 0; kk < 128; kk++) acc += xs[r][kk] * ws[k][kk];
        __syncthreads();
    }
    g_feats[(tb0 + r) * KT + k] = acc + lb[k];
}

// ---------------- CRF (round-1 verbatim) ----------------
__global__ void crf_k(const int* __restrict__ tokens, const int* __restrict__ tags,
                      const int* __restrict__ lengths, const float* __restrict__ trans)
{
    const int b = blockIdx.x;
    const int k = threadIdx.x;              // 0..31
    __shared__ float al[KT];

    float tr[KT];
#pragma unroll
    for (int j = 0; j < KT; j++) tr[j] = trans[k * KT + j];

    al[k] = (k == 30) ? 0.f : NEGV;
    __syncwarp();

    for (int t = 0; t < T_; t++) {
        float m = -3.4e38f;
#pragma unroll
        for (int j = 0; j < KT; j++) m = fmaxf(m, al[j] + tr[j]);
        float ss = 0.f;
#pragma unroll
        for (int j = 0; j < KT; j++) ss += __expf(al[j] + tr[j] - m);
        float nw = m + __logf(ss) + g_feats[((size_t)t * B_ + b) * KT + k];
        int msk = tokens[t * B_ + b] > 0;
        __syncwarp();
        if (msk) al[k] = nw;
        __syncwarp();
    }

    float v = al[k] + trans[31 * KT + k];
    float m = v;
#pragma unroll
    for (int o = 16; o; o >>= 1) m = fmaxf(m, __shfl_xor_sync(0xffffffffu, m, o));
    float e = __expf(v - m);
#pragma unroll
    for (int o = 16; o; o >>= 1) e += __shfl_xor_sync(0xffffffffu, e, o);
    float logz = m + __logf(e);

    float gl = 0.f;
    for (int t = k; t < T_; t += 32) {
        int cur  = tags[t * B_ + b];
        int prev = (t == 0) ? 30 : tags[(t - 1) * B_ + b];
        float mm = (tokens[t * B_ + b] > 0) ? 1.f : 0.f;
        gl += mm * (trans[cur * KT + prev] + g_feats[((size_t)t * B_ + b) * KT + cur]);
    }
#pragma unroll
    for (int o = 16; o; o >>= 1) gl += __shfl_xor_sync(0xffffffffu, gl, o);
    gl += trans[31 * KT + tags[(T_ - 1) * B_ + b]];

    if (k == 0) g_part[b] = (logz - gl) / (float)lengths[b];
}

__global__ void out_k(float* __restrict__ out) {
    __shared__ float s[B_];
    s[threadIdx.x] = g_part[threadIdx.x];
    __syncthreads();
    for (int o = 32; o; o >>= 1) {
        if (threadIdx.x < o) s[threadIdx.x] += s[threadIdx.x + o];
        __syncthreads();
    }
    if (threadIdx.x == 0) out[0] = s[0];
}

// ---------------- launcher ----------------
extern "C" void kernel_launch(void* const* d_in, const int* in_sizes, int n_in,
                              void* d_out, int out_size)
{
    const int*   tokens  = (const int*)d_in[0];
    const int*   tags    = (const int*)d_in[1];
    const int*   lengths = (const int*)d_in[2];
    const float* embed   = (const float*)d_in[3];
    const float* wih0    = (const float*)d_in[4];
    const float* whh0    = (const float*)d_in[5];
    const float* b0      = (const float*)d_in[6];
    const float* wih1    = (const float*)d_in[7];
    const float* whh1    = (const float*)d_in[8];
    const float* b1      = (const float*)d_in[9];
    const float* lin_w   = (const float*)d_in[10];
    const float* lin_b   = (const float*)d_in[11];
    const float* trans   = (const float*)d_in[12];
    float* out = (float*)d_out;

    cudaFuncSetAttribute(lstm_rec_k<0>, cudaFuncAttributeMaxDynamicSharedMemorySize, REC_SMEM);
    cudaFuncSetAttribute(lstm_rec_k<1>, cudaFuncAttributeMaxDynamicSharedMemorySize, REC_SMEM);

    cvt_k<<<6144, 256>>>(wih0, wih1);

    const int n4 = T_ * B_ * E_ / 4;
    embed_k<<<(n4 + 255) / 256, 256>>>(tokens, embed);

    gemm_xp_k<0><<<dim3(16, 128, 2), 256>>>(b0);
    lstm_rec_k<0><<<128, 256, REC_SMEM>>>(whh0);

    gemm_xp_k<1><<<dim3(16, 128, 2), 256>>>(b1);
    lstm_rec_k<1><<<128, 256, REC_SMEM>>>(whh1);

    feats_k<<<T_ * B_ / 8, 256>>>(lin_w, lin_b);
    crf_k<<<B_, 32>>>(tokens, tags, lengths, trans);
    out_k<<<1, B_>>>(out);
}

// round 15
// speedup vs baseline: 1.1487x; 1.1487x over previous
#include <cuda_runtime.h>
#include <cuda_bf16.h>
#include <cstdint>

#define T_  256
#define B_  64
#define E_  512
#define H_  512
#define KT  32      // num tags
#define G4  2048    // 4*H
#define NEGV -100000.0f

typedef __nv_bfloat16 bf16;

// ---------------- scratch (static device allocations are allowed) ----------------
__device__ __align__(16) bf16 g_x0b[(size_t)T_*B_*E_];    // embedded input bf16 [tb][512]
__device__ __align__(16) bf16 g_x1b[(size_t)T_*B_*2*H_];  // layer0 out bf16 [tb][1024]
__device__ __align__(16) bf16 g_x2b[(size_t)T_*B_*2*H_];  // layer1 out bf16 [tb][1024]
__device__ __align__(16) bf16 g_wih0b[(size_t)2*G4*E_];   // wih0 bf16
__device__ __align__(16) bf16 g_wih1b[(size_t)2*G4*2*H_]; // wih1 bf16
__device__ float g_xp[(size_t)2*T_*G4*B_];        // input-proj gates fp32 [d][t][g][b]
__device__ __align__(16) bf16 g_hbb[(size_t)2*2*B_*H_];  // h bf16, ping-pong: [par][d][b][k]
__device__ float g_feats[(size_t)T_*B_*KT];       // emission scores
__device__ float g_part[B_];
__device__ __align__(256) unsigned g_flag[2][64]; // per-block arrival flags (monotonic)
__device__ unsigned g_bar_gen[2];                 // published generation (monotonic)

// ---------------- helpers ----------------
__device__ __forceinline__ void mma_bf(float* c, uint32_t a0, uint32_t a1,
                                       uint32_t a2, uint32_t a3,
                                       uint32_t b0, uint32_t b1)
{
    asm volatile(
        "mma.sync.aligned.m16n8k16.row.col.f32.bf16.bf16.f32 "
        "{%0,%1,%2,%3},{%4,%5,%6,%7},{%8,%9},{%0,%1,%2,%3};"
        : "+f"(c[0]), "+f"(c[1]), "+f"(c[2]), "+f"(c[3])
        : "r"(a0), "r"(a1), "r"(a2), "r"(a3), "r"(b0), "r"(b1));
}

__device__ __forceinline__ float sigf(float x) {
    return 1.f / (1.f + __expf(-x));
}

// grid barrier among the 64 blocks of one direction (round-12 PROVEN version).
// Arrival = plain store of a monotonic generation to the block's own flag slot;
// the leader block (sole reader of the flag lines) polls all 64 flags with 64
// threads, then publishes the generation; followers poll the generation word.
__device__ __forceinline__ void gbarrier(int d, int bid, bool leader, unsigned gen) {
    __syncthreads();
    if (leader) {
        if (threadIdx.x == 0) {
            __threadfence();
            *((volatile unsigned*)&g_flag[d][bid]) = gen;
        }
        if (threadIdx.x < 64) {
            while (*((volatile unsigned*)&g_flag[d][threadIdx.x]) < gen) { __nanosleep(8); }
        }
        __syncthreads();
        if (threadIdx.x == 0) {
            *((volatile unsigned*)&g_bar_gen[d]) = gen;
            __threadfence();
        }
    } else if (threadIdx.x == 0) {
        __threadfence();
        *((volatile unsigned*)&g_flag[d][bid]) = gen;
        while (*((volatile unsigned*)&g_bar_gen[d]) < gen) { __nanosleep(16); }
        __threadfence();
    }
    __syncthreads();
}

// ---------------- weight conversion fp32 -> bf16 (wih only) ----------------
__global__ void cvt_k(const float* __restrict__ wih0, const float* __restrict__ wih1) {
    int i = blockIdx.x * 256 + threadIdx.x;   // float4 index
    const float* s; bf16* dst; int off;
    if (i < 524288)       { s = wih0; dst = g_wih0b; off = i; }
    else if (i < 1572864) { s = wih1; dst = g_wih1b; off = i - 524288; }
    else return;
    float4 v = ((const float4*)s)[off];
    __nv_bfloat162* o = (__nv_bfloat162*)dst + (size_t)off * 2;
    o[0] = __floats2bfloat162_rn(v.x, v.y);
    o[1] = __floats2bfloat162_rn(v.z, v.w);
}

// ---------------- embedding lookup -> bf16 ----------------
__global__ void embed_k(const int* __restrict__ tokens, const float* __restrict__ embed) {
    size_t i = (size_t)blockIdx.x * blockDim.x + threadIdx.x;   // float4 index
    if (i >= (size_t)T_ * B_ * E_ / 4) return;
    size_t el = i * 4;
    size_t tb = el / E_;
    int    e  = (int)(el % E_);
    const float4 v = *(const float4*)(embed + (size_t)tokens[tb] * E_ + e);
    __nv_bfloat162* o = (__nv_bfloat162*)(g_x0b + el);
    o[0] = __floats2bfloat162_rn(v.x, v.y);
    o[1] = __floats2bfloat162_rn(v.z, v.w);
}

// ---------------- input projection GEMM: 2 timesteps per block (N=128) ----------
// W tile re-read halved vs round 11. X rows for (t0, t0+1) are contiguous, so
// Bs staging is one coalesced 128-row copy. Register prefetch kept.
template<int L>
__global__ __launch_bounds__(256) void gemm_xp_k(const float* __restrict__ bias)
{
    constexpr int KSZ = (L == 0) ? 512 : 1024;
    const bf16* X = (L == 0) ? g_x0b : g_x1b;
    const bf16* Wb = (L == 0) ? g_wih0b : g_wih1b;

    __shared__ __align__(16) bf16 As[128][40];
    __shared__ __align__(16) bf16 Bs[128][40];   // two 64-row timestep tiles

    const int d = blockIdx.z, t0 = blockIdx.y * 2, gbase = blockIdx.x * 128;
    const bf16* Wd = Wb + (size_t)d * G4 * KSZ;
    const bf16* Xt = X + (size_t)t0 * B_ * KSZ;   // 128 contiguous tb rows

    const int tid = threadIdx.x, warp = tid >> 5, lane = tid & 31;
    const int wm = (warp >> 1) * 32, wn = (warp & 1) * 32;
    const int gid = lane >> 2, tig = lane & 3;

    float acc[2][2][4][4];    // [tt][mt][nt][4]
#pragma unroll
    for (int a = 0; a < 2; a++)
#pragma unroll
        for (int b = 0; b < 2; b++)
#pragma unroll
            for (int c = 0; c < 4; c++)
#pragma unroll
                for (int e = 0; e < 4; e++) acc[a][b][c][e] = 0.f;

    const int row0 = tid >> 2;          // 0..63
    const int c8   = (tid & 3) * 8;

    uint4 ra0, ra1, rb0, rb1;
    auto LD = [&](int k0) {
        ra0 = *(const uint4*)(Wd + (size_t)(gbase + row0) * KSZ + k0 + c8);
        ra1 = *(const uint4*)(Wd + (size_t)(gbase + row0 + 64) * KSZ + k0 + c8);
        rb0 = *(const uint4*)(Xt + (size_t)row0 * KSZ + k0 + c8);
        rb1 = *(const uint4*)(Xt + (size_t)(row0 + 64) * KSZ + k0 + c8);
    };
    LD(0);

    for (int k0 = 0; k0 < KSZ; k0 += 32) {
        *(uint4*)&As[row0][c8]      = ra0;
        *(uint4*)&As[row0 + 64][c8] = ra1;
        *(uint4*)&Bs[row0][c8]      = rb0;
        *(uint4*)&Bs[row0 + 64][c8] = rb1;
        __syncthreads();
        if (k0 + 32 < KSZ) LD(k0 + 32);     // prefetch next chunk (hides under mma)
#pragma unroll
        for (int ks = 0; ks < 2; ks++) {
            const int kk = ks * 16 + 2 * tig;
            uint32_t a[2][4];
#pragma unroll
            for (int mt = 0; mt < 2; mt++) {
                int r0 = wm + mt * 16 + gid;
                a[mt][0] = *(const uint32_t*)&As[r0][kk];
                a[mt][1] = *(const uint32_t*)&As[r0 + 8][kk];
                a[mt][2] = *(const uint32_t*)&As[r0][kk + 8];
                a[mt][3] = *(const uint32_t*)&As[r0 + 8][kk + 8];
            }
#pragma unroll
            for (int tt = 0; tt < 2; tt++) {
#pragma unroll
                for (int nt = 0; nt < 4; nt++) {
                    int ci = tt * 64 + wn + nt * 8 + gid;
                    uint32_t b0 = *(const uint32_t*)&Bs[ci][kk];
                    uint32_t b1 = *(const uint32_t*)&Bs[ci][kk + 8];
                    mma_bf(acc[tt][0][nt], a[0][0], a[0][1], a[0][2], a[0][3], b0, b1);
                    mma_bf(acc[tt][1][nt], a[1][0], a[1][1], a[1][2], a[1][3], b0, b1);
                }
            }
        }
        __syncthreads();
    }
#pragma unroll
    for (int tt = 0; tt < 2; tt++) {
        float* XP = g_xp + ((size_t)(d * T_ + t0 + tt) * G4) * B_;
#pragma unroll
        for (int mt = 0; mt < 2; mt++) {
            int r0 = gbase + wm + mt * 16 + gid;
            float bb0 = bias[(size_t)d * G4 + r0];
            float bb1 = bias[(size_t)d * G4 + r0 + 8];
#pragma unroll
            for (int nt = 0; nt < 4; nt++) {
                int c = wn + nt * 8 + tig * 2;
                float2 v0 = make_float2(acc[tt][mt][nt][0] + bb0, acc[tt][mt][nt][1] + bb0);
                float2 v1 = make_float2(acc[tt][mt][nt][2] + bb1, acc[tt][mt][nt][3] + bb1);
                *(float2*)(XP + (size_t)r0 * B_ + c)       = v0;
                *(float2*)(XP + (size_t)(r0 + 8) * B_ + c) = v1;
            }
        }
    }
}

// ---------------- recurrence kernel (round-12 VERBATIM) --------------------------
// smem: whh 32x520 bf16 + h 64x520 bf16 + z 32x68 f32 = 108544 B
#define REC_SMEM ((32 * 520 + 64 * 520) * 2 + 32 * 68 * 4)

template<int L>
__global__ __launch_bounds__(256, 1) void lstm_rec_k(const float* __restrict__ Whh)
{
    bf16* Xout = (L == 0) ? g_x1b : g_x2b;
    extern __shared__ char smraw[];
    bf16*  whh_s = (bf16*)smraw;                     // [32][520]
    bf16*  h_s   = (bf16*)(smraw + 32 * 520 * 2);    // [64][520]
    float* z_s   = (float*)(smraw + (32 + 64) * 520 * 2); // [32][68]

    const int blk = blockIdx.x;
    const int d = blk >> 6;
    const int bid = blk & 63;
    const int jbase = bid * 8;
    const bool leader = bid == 0;
    const int tid = threadIdx.x, warp = tid >> 5, lane = tid & 31;
    const int gid = lane >> 2, tig = lane & 3;
    const int wm = (warp >> 2) * 16, wn = (warp & 3) * 16;

    // read generation base (stable at kernel entry; monotonic across replays)
    __shared__ unsigned s_base;
    if (tid == 0) s_base = *((volatile unsigned*)&g_bar_gen[d]);

    const float* Wd = Whh + (size_t)d * G4 * H_;

    // load + convert this block's 32 Whh rows (local m = q*8+jl <-> q*512+jbase+jl)
    for (int i = tid; i < 32 * 128; i += 256) {
        int m = i >> 7, c4 = (i & 127) * 4;
        int grow = (m >> 3) * 512 + jbase + (m & 7);
        float4 v = *(const float4*)(Wd + (size_t)grow * H_ + c4);
        __nv_bfloat162 p0 = __floats2bfloat162_rn(v.x, v.y);
        __nv_bfloat162 p1 = __floats2bfloat162_rn(v.z, v.w);
        uint2 pk = make_uint2(*(uint32_t*)&p0, *(uint32_t*)&p1);
        *(uint2*)&whh_s[m * 520 + c4] = pk;
    }

    // per-thread cells: b = tid>>2 (0..63), j0 = (tid&3)*2
    const int b  = tid >> 2;
    const int j0 = (tid & 3) * 2;
    float cst[2] = {0.f, 0.f};

    // zero h_{-1} into parity buffer 0
    *(__nv_bfloat162*)(g_hbb + ((size_t)(0 * 2 + d) * B_ + b) * H_ + jbase + j0) =
        __floats2bfloat162_rn(0.f, 0.f);

    __syncthreads();
    unsigned gen = s_base + 1;

    gbarrier(d, bid, leader, gen); gen++;

    for (int s = 0; s < T_; s++) {
        const int t = (d == 0) ? s : (T_ - 1 - s);
        const int rb = s & 1;          // read parity
        const int wb = rb ^ 1;         // write parity
        const bf16* hsrc = g_hbb + (size_t)(rb * 2 + d) * B_ * H_;

        // hoisted xp gate loads (8 independent fp32; hide under staging + mma)
        const float* xpb = g_xp + ((size_t)(d * T_ + t) * G4 + jbase) * B_;
        float xv[4][2];
#pragma unroll
        for (int q = 0; q < 4; q++)
#pragma unroll
            for (int u = 0; u < 2; u++)
                xv[q][u] = xpb[(size_t)(q * 512 + j0 + u) * B_ + b];

        // stage FULL h (64 x 512 bf16) once: 16 uint4 per thread
#pragma unroll
        for (int p = 0; p < 16; p++) {
            int idx = p * 256 + tid;
            int row = idx >> 6;
            int c8  = (idx & 63) * 8;
            *(uint4*)&h_s[row * 520 + c8] = *(const uint4*)(hsrc + (size_t)row * H_ + c8);
        }
        __syncthreads();

        float z[2][4] = {{0.f,0.f,0.f,0.f},{0.f,0.f,0.f,0.f}};
#pragma unroll 8
        for (int ks = 0; ks < 32; ks++) {
            const int kk = ks * 16 + 2 * tig;
            const int ar = wm + gid;
            uint32_t a0 = *(const uint32_t*)&whh_s[ar * 520 + kk];
            uint32_t a1 = *(const uint32_t*)&whh_s[(ar + 8) * 520 + kk];
            uint32_t a2 = *(const uint32_t*)&whh_s[ar * 520 + kk + 8];
            uint32_t a3 = *(const uint32_t*)&whh_s[(ar + 8) * 520 + kk + 8];
#pragma unroll
            for (int nt = 0; nt < 2; nt++) {
                int nc = wn + nt * 8 + gid;
                uint32_t b0 = *(const uint32_t*)&h_s[nc * 520 + kk];
                uint32_t b1 = *(const uint32_t*)&h_s[nc * 520 + kk + 8];
                mma_bf(z[nt], a0, a1, a2, a3, b0, b1);
            }
        }

        // z fragments -> smem
#pragma unroll
        for (int nt = 0; nt < 2; nt++) {
            int cc = wn + nt * 8 + tig * 2;
            *(float2*)&z_s[(wm + gid) * 68 + cc]     = make_float2(z[nt][0], z[nt][1]);
            *(float2*)&z_s[(wm + gid + 8) * 68 + cc] = make_float2(z[nt][2], z[nt][3]);
        }
        __syncthreads();

        // gates + state update for cells (jbase+j0, b), (jbase+j0+1, b)
        float hv[2];
#pragma unroll
        for (int u = 0; u < 2; u++) {
            int j = j0 + u;
            float zi = z_s[(j)      * 68 + b] + xv[0][u];
            float zf = z_s[(8 + j)  * 68 + b] + xv[1][u];
            float zg = z_s[(16 + j) * 68 + b] + xv[2][u];
            float zo = z_s[(24 + j) * 68 + b] + xv[3][u];
            float iv = sigf(zi), fv = sigf(zf), ov = sigf(zo);
            float gv = tanhf(zg);
            cst[u] = fv * cst[u] + iv * gv;
            hv[u] = ov * tanhf(cst[u]);
        }
        __nv_bfloat162 hb = __floats2bfloat162_rn(hv[0], hv[1]);
        *(__nv_bfloat162*)(g_hbb + ((size_t)(wb * 2 + d) * B_ + b) * H_ + jbase + j0) = hb;
        *(__nv_bfloat162*)(Xout + ((size_t)t * B_ + b) * (2 * H_) + d * H_ + jbase + j0) = hb;

        gbarrier(d, bid, leader, gen); gen++;
    }
}

// ---------------- emission scores (round-8 verbatim) ----------------
__global__ __launch_bounds__(256) void feats_k(const float* __restrict__ lw,
                                               const float* __restrict__ lb)
{
    __shared__ float xs[8][129];
    __shared__ float ws[32][129];
    const int tid = threadIdx.x;
    const int r = tid >> 5, k = tid & 31;
    const size_t tb0 = (size_t)blockIdx.x * 8;
    float acc = 0.f;
    for (int c0 = 0; c0 < 2 * H_; c0 += 128) {
        for (int i = tid; i < 8 * 128; i += 256)
            xs[i >> 7][i & 127] =
                __bfloat162float(g_x2b[(tb0 + (i >> 7)) * (2 * H_) + c0 + (i & 127)]);
        for (int i = tid; i < 32 * 128; i += 256)
            ws[i >> 7][i & 127] = lw[(size_t)(i >> 7) * (2 * H_) + c0 + (i & 127)];
        __syncthreads();
#pragma unroll 16
        for (int kk = 0; kk < 128; kk++) acc += xs[r][kk] * ws[k][kk];
        __syncthreads();
    }
    g_feats[(tb0 + r) * KT + k] = acc + lb[k];
}

// ---------------- CRF (round-1 verbatim) ----------------
__global__ void crf_k(const int* __restrict__ tokens, const int* __restrict__ tags,
                      const int* __restrict__ lengths, const float* __restrict__ trans)
{
    const int b = blockIdx.x;
    const int k = threadIdx.x;              // 0..31
    __shared__ float al[KT];

    float tr[KT];
#pragma unroll
    for (int j = 0; j < KT; j++) tr[j] = trans[k * KT + j];

    al[k] = (k == 30) ? 0.f : NEGV;
    __syncwarp();

    for (int t = 0; t < T_; t++) {
        float m = -3.4e38f;
#pragma unroll
        for (int j = 0; j < KT; j++) m = fmaxf(m, al[j] + tr[j]);
        float ss = 0.f;
#pragma unroll
        for (int j = 0; j < KT; j++) ss += __expf(al[j] + tr[j] - m);
        float nw = m + __logf(ss) + g_feats[((size_t)t * B_ + b) * KT + k];
        int msk = tokens[t * B_ + b] > 0;
        __syncwarp();
        if (msk) al[k] = nw;
        __syncwarp();
    }

    float v = al[k] + trans[31 * KT + k];
    float m = v;
#pragma unroll
    for (int o = 16; o; o >>= 1) m = fmaxf(m, __shfl_xor_sync(0xffffffffu, m, o));
    float e = __expf(v - m);
#pragma unroll
    for (int o = 16; o; o >>= 1) e += __shfl_xor_sync(0xffffffffu, e, o);
    float logz = m + __logf(e);

    float gl = 0.f;
    for (int t = k; t < T_; t += 32) {
        int cur  = tags[t * B_ + b];
        int prev = (t == 0) ? 30 : tags[(t - 1) * B_ + b];
        float mm = (tokens[t * B_ + b] > 0) ? 1.f : 0.f;
        gl += mm * (trans[cur * KT + prev] + g_feats[((size_t)t * B_ + b) * KT + cur]);
    }
#pragma unroll
    for (int o = 16; o; o >>= 1) gl += __shfl_xor_sync(0xffffffffu, gl, o);
    gl += trans[31 * KT + tags[(T_ - 1) * B_ + b]];

    if (k == 0) g_part[b] = (logz - gl) / (float)lengths[b];
}

__global__ void out_k(float* __restrict__ out) {
    __shared__ float s[B_];
    s[threadIdx.x] = g_part[threadIdx.x];
    __syncthreads();
    for (int o = 32; o; o >>= 1) {
        if (threadIdx.x < o) s[threadIdx.x] += s[threadIdx.x + o];
        __syncthreads();
    }
    if (threadIdx.x == 0) out[0] = s[0];
}

// ---------------- launcher ----------------
extern "C" void kernel_launch(void* const* d_in, const int* in_sizes, int n_in,
                              void* d_out, int out_size)
{
    const int*   tokens  = (const int*)d_in[0];
    const int*   tags    = (const int*)d_in[1];
    const int*   lengths = (const int*)d_in[2];
    const float* embed   = (const float*)d_in[3];
    const float* wih0    = (const float*)d_in[4];
    const float* whh0    = (const float*)d_in[5];
    const float* b0      = (const float*)d_in[6];
    const float* wih1    = (const float*)d_in[7];
    const float* whh1    = (const float*)d_in[8];
    const float* b1      = (const float*)d_in[9];
    const float* lin_w   = (const float*)d_in[10];
    const float* lin_b   = (const float*)d_in[11];
    const float* trans   = (const float*)d_in[12];
    float* out = (float*)d_out;

    cudaFuncSetAttribute(lstm_rec_k<0>, cudaFuncAttributeMaxDynamicSharedMemorySize, REC_SMEM);
    cudaFuncSetAttribute(lstm_rec_k<1>, cudaFuncAttributeMaxDynamicSharedMemorySize, REC_SMEM);

    cvt_k<<<6144, 256>>>(wih0, wih1);

    const int n4 = T_ * B_ * E_ / 4;
    embed_k<<<(n4 + 255) / 256, 256>>>(tokens, embed);

    gemm_xp_k<0><<<dim3(16, 128, 2), 256>>>(b0);
    lstm_rec_k<0><<<128, 256, REC_SMEM>>>(whh0);

    gemm_xp_k<1><<<dim3(16, 128, 2), 256>>>(b1);
    lstm_rec_k<1><<<128, 256, REC_SMEM>>>(whh1);

    feats_k<<<T_ * B_ / 8, 256>>>(lin_w, lin_b);
    crf_k<<<B_, 32>>>(tokens, tags, lengths, trans);
    out_k<<<1, B_>>>(out);
}

// round 16
// speedup vs baseline: 1.5814x; 1.3767x over previous
#include <cuda_runtime.h>
#include <cuda_bf16.h>
#include <cstdint>

#define T_  256
#define B_  64
#define E_  512
#define H_  512
#define KT  32      // num tags
#define G4  2048    // 4*H
#define NEGV -100000.0f

typedef __nv_bfloat16 bf16;

// ---------------- scratch (static device allocations are allowed) ----------------
__device__ __align__(16) bf16 g_x0b[(size_t)T_*B_*E_];    // embedded input bf16 [tb][512]
__device__ __align__(16) bf16 g_x1b[(size_t)T_*B_*2*H_];  // layer0 out bf16 [tb][1024]
__device__ __align__(16) bf16 g_x2b[(size_t)T_*B_*2*H_];  // layer1 out bf16 [tb][1024]
__device__ __align__(16) bf16 g_wih0b[(size_t)2*G4*E_];   // wih0 bf16
__device__ __align__(16) bf16 g_wih1b[(size_t)2*G4*2*H_]; // wih1 bf16
__device__ float g_xp[(size_t)2*T_*G4*B_];        // input-proj gates fp32 [d][t][g][b]
__device__ __align__(16) bf16 g_hbb[(size_t)2*2*B_*H_];  // h bf16, ping-pong: [par][d][b][k]
__device__ float g_feats[(size_t)T_*B_*KT];       // emission scores
__device__ float g_part[B_];
__device__ __align__(256) unsigned g_flag[2][64]; // per-block arrival flags (monotonic)
__device__ unsigned g_bar_gen[2];                 // published generation (monotonic)

// ---------------- helpers ----------------
__device__ __forceinline__ void mma_bf(float* c, uint32_t a0, uint32_t a1,
                                       uint32_t a2, uint32_t a3,
                                       uint32_t b0, uint32_t b1)
{
    asm volatile(
        "mma.sync.aligned.m16n8k16.row.col.f32.bf16.bf16.f32 "
        "{%0,%1,%2,%3},{%4,%5,%6,%7},{%8,%9},{%0,%1,%2,%3};"
        : "+f"(c[0]), "+f"(c[1]), "+f"(c[2]), "+f"(c[3])
        : "r"(a0), "r"(a1), "r"(a2), "r"(a3), "r"(b0), "r"(b1));
}

__device__ __forceinline__ float sigf(float x) {
    return 1.f / (1.f + __expf(-x));
}

// ---- split-phase grid barrier (round-12 topology: leader reads flags) ----------
// arrive: all threads synced, then tid0 fences (release) + stores the block's
// own flag. wait: leader polls all 64 flags (sole reader), publishes gen;
// followers poll the gen word. Work placed between arrive and wait overlaps
// with the barrier's detection/release chain.
__device__ __forceinline__ void gbar_arrive(int d, int bid, unsigned gen) {
    __syncthreads();
    if (threadIdx.x == 0) {
        __threadfence();                              // h stores visible first
        *((volatile unsigned*)&g_flag[d][bid]) = gen;
    }
}

__device__ __forceinline__ void gbar_wait(int d, bool leader, unsigned gen) {
    if (leader) {
        if (threadIdx.x < 64) {
            while (*((volatile unsigned*)&g_flag[d][threadIdx.x]) < gen) { __nanosleep(8); }
        }
        __syncthreads();
        if (threadIdx.x == 0) {
            *((volatile unsigned*)&g_bar_gen[d]) = gen;
            __threadfence();
        }
    } else {
        if (threadIdx.x == 0) {
            while (*((volatile unsigned*)&g_bar_gen[d]) < gen) { __nanosleep(16); }
            __threadfence();                          // acquire
        }
    }
    __syncthreads();
}

// ---------------- weight conversion fp32 -> bf16 (wih only) ----------------
__global__ void cvt_k(const float* __restrict__ wih0, const float* __restrict__ wih1) {
    int i = blockIdx.x * 256 + threadIdx.x;   // float4 index
    const float* s; bf16* dst; int off;
    if (i < 524288)       { s = wih0; dst = g_wih0b; off = i; }
    else if (i < 1572864) { s = wih1; dst = g_wih1b; off = i - 524288; }
    else return;
    float4 v = ((const float4*)s)[off];
    __nv_bfloat162* o = (__nv_bfloat162*)dst + (size_t)off * 2;
    o[0] = __floats2bfloat162_rn(v.x, v.y);
    o[1] = __floats2bfloat162_rn(v.z, v.w);
}

// ---------------- embedding lookup -> bf16 ----------------
__global__ void embed_k(const int* __restrict__ tokens, const float* __restrict__ embed) {
    size_t i = (size_t)blockIdx.x * blockDim.x + threadIdx.x;   // float4 index
    if (i >= (size_t)T_ * B_ * E_ / 4) return;
    size_t el = i * 4;
    size_t tb = el / E_;
    int    e  = (int)(el % E_);
    const float4 v = *(const float4*)(embed + (size_t)tokens[tb] * E_ + e);
    __nv_bfloat162* o = (__nv_bfloat162*)(g_x0b + el);
    o[0] = __floats2bfloat162_rn(v.x, v.y);
    o[1] = __floats2bfloat162_rn(v.z, v.w);
}

// ---------------- input projection GEMM (round-11 PROVEN version) ---------------
template<int L>
__global__ __launch_bounds__(256) void gemm_xp_k(const float* __restrict__ bias)
{
    constexpr int KSZ = (L == 0) ? 512 : 1024;
    const bf16* X = (L == 0) ? g_x0b : g_x1b;
    const bf16* Wb = (L == 0) ? g_wih0b : g_wih1b;

    __shared__ __align__(16) bf16 As[128][40];
    __shared__ __align__(16) bf16 Bs[64][40];

    const int d = blockIdx.z, t = blockIdx.y, gbase = blockIdx.x * 128;
    const bf16* Wd = Wb + (size_t)d * G4 * KSZ;
    const bf16* Xt = X + (size_t)t * B_ * KSZ;

    const int tid = threadIdx.x, warp = tid >> 5, lane = tid & 31;
    const int wm = (warp >> 1) * 32, wn = (warp & 1) * 32;
    const int gid = lane >> 2, tig = lane & 3;

    float acc[2][4][4];
#pragma unroll
    for (int a = 0; a < 2; a++)
#pragma unroll
        for (int b = 0; b < 4; b++)
#pragma unroll
            for (int c = 0; c < 4; c++) acc[a][b][c] = 0.f;

    const int row0 = tid >> 2;          // 0..63
    const int c8   = (tid & 3) * 8;

    uint4 ra0, ra1, rbv;
    auto LD = [&](int k0) {
        ra0 = *(const uint4*)(Wd + (size_t)(gbase + row0) * KSZ + k0 + c8);
        ra1 = *(const uint4*)(Wd + (size_t)(gbase + row0 + 64) * KSZ + k0 + c8);
        rbv = *(const uint4*)(Xt + (size_t)row0 * KSZ + k0 + c8);
    };
    LD(0);

    for (int k0 = 0; k0 < KSZ; k0 += 32) {
        *(uint4*)&As[row0][c8]      = ra0;
        *(uint4*)&As[row0 + 64][c8] = ra1;
        *(uint4*)&Bs[row0][c8]      = rbv;
        __syncthreads();
        if (k0 + 32 < KSZ) LD(k0 + 32);     // prefetch next chunk (hides under mma)
#pragma unroll
        for (int ks = 0; ks < 2; ks++) {
            const int kk = ks * 16 + 2 * tig;
            uint32_t a[2][4];
#pragma unroll
            for (int mt = 0; mt < 2; mt++) {
                int r0 = wm + mt * 16 + gid;
                a[mt][0] = *(const uint32_t*)&As[r0][kk];
                a[mt][1] = *(const uint32_t*)&As[r0 + 8][kk];
                a[mt][2] = *(const uint32_t*)&As[r0][kk + 8];
                a[mt][3] = *(const uint32_t*)&As[r0 + 8][kk + 8];
            }
#pragma unroll
            for (int nt = 0; nt < 4; nt++) {
                int ci = wn + nt * 8 + gid;
                uint32_t b0 = *(const uint32_t*)&Bs[ci][kk];
                uint32_t b1 = *(const uint32_t*)&Bs[ci][kk + 8];
                mma_bf(acc[0][nt], a[0][0], a[0][1], a[0][2], a[0][3], b0, b1);
                mma_bf(acc[1][nt], a[1][0], a[1][1], a[1][2], a[1][3], b0, b1);
            }
        }
        __syncthreads();
    }
    float* XP = g_xp + ((size_t)(d * T_ + t) * G4) * B_;
#pragma unroll
    for (int mt = 0; mt < 2; mt++) {
        int r0 = gbase + wm + mt * 16 + gid;
        float bb0 = bias[(size_t)d * G4 + r0];
        float bb1 = bias[(size_t)d * G4 + r0 + 8];
#pragma unroll
        for (int nt = 0; nt < 4; nt++) {
            int c = wn + nt * 8 + tig * 2;
            float2 v0 = make_float2(acc[mt][nt][0] + bb0, acc[mt][nt][1] + bb0);
            float2 v1 = make_float2(acc[mt][nt][2] + bb1, acc[mt][nt][3] + bb1);
            *(float2*)(XP + (size_t)r0 * B_ + c)       = v0;
            *(float2*)(XP + (size_t)(r0 + 8) * B_ + c) = v1;
        }
    }
}

// ---------------- recurrence kernel (round-12 + split-phase barrier) -------------
// smem: whh 32x520 bf16 + h 64x520 bf16 + z 32x68 f32 = 108544 B
#define REC_SMEM ((32 * 520 + 64 * 520) * 2 + 32 * 68 * 4)

template<int L>
__global__ __launch_bounds__(256, 1) void lstm_rec_k(const float* __restrict__ Whh)
{
    bf16* Xout = (L == 0) ? g_x1b : g_x2b;
    extern __shared__ char smraw[];
    bf16*  whh_s = (bf16*)smraw;                     // [32][520]
    bf16*  h_s   = (bf16*)(smraw + 32 * 520 * 2);    // [64][520]
    float* z_s   = (float*)(smraw + (32 + 64) * 520 * 2); // [32][68]

    const int blk = blockIdx.x;
    const int d = blk >> 6;
    const int bid = blk & 63;
    const int jbase = bid * 8;
    const bool leader = bid == 0;
    const int tid = threadIdx.x, warp = tid >> 5, lane = tid & 31;
    const int gid = lane >> 2, tig = lane & 3;
    const int wm = (warp >> 2) * 16, wn = (warp & 3) * 16;

    // read generation base (stable at kernel entry; monotonic across replays)
    __shared__ unsigned s_base;
    if (tid == 0) s_base = *((volatile unsigned*)&g_bar_gen[d]);

    const float* Wd = Whh + (size_t)d * G4 * H_;

    // load + convert this block's 32 Whh rows (local m = q*8+jl <-> q*512+jbase+jl)
    for (int i = tid; i < 32 * 128; i += 256) {
        int m = i >> 7, c4 = (i & 127) * 4;
        int grow = (m >> 3) * 512 + jbase + (m & 7);
        float4 v = *(const float4*)(Wd + (size_t)grow * H_ + c4);
        __nv_bfloat162 p0 = __floats2bfloat162_rn(v.x, v.y);
        __nv_bfloat162 p1 = __floats2bfloat162_rn(v.z, v.w);
        uint2 pk = make_uint2(*(uint32_t*)&p0, *(uint32_t*)&p1);
        *(uint2*)&whh_s[m * 520 + c4] = pk;
    }

    // per-thread cells: b = tid>>2 (0..63), j0 = (tid&3)*2
    const int b  = tid >> 2;
    const int j0 = (tid & 3) * 2;
    float cst[2] = {0.f, 0.f};

    // zero h_{-1} into parity buffer 0
    *(__nv_bfloat162*)(g_hbb + ((size_t)(0 * 2 + d) * B_ + b) * H_ + jbase + j0) =
        __floats2bfloat162_rn(0.f, 0.f);

    __syncthreads();
    unsigned gen = s_base + 1;

    // xp prefetch helper: loads the 8 gate pre-activations for timestep index s
    float xv[4][2];
    auto xp_prefetch = [&](int s) {
        const int t = (d == 0) ? s : (T_ - 1 - s);
        const float* xpb = g_xp + ((size_t)(d * T_ + t) * G4 + jbase) * B_;
#pragma unroll
        for (int q = 0; q < 4; q++)
#pragma unroll
            for (int u = 0; u < 2; u++)
                xv[q][u] = xpb[(size_t)(q * 512 + j0 + u) * B_ + b];
    };

    // first barrier: overlap the s=0 xp loads with the barrier chain
    gbar_arrive(d, bid, gen);
    xp_prefetch(0);
    gbar_wait(d, leader, gen);
    gen++;

    for (int s = 0; s < T_; s++) {
        const int t = (d == 0) ? s : (T_ - 1 - s);
        const int rb = s & 1;          // read parity
        const int wb = rb ^ 1;         // write parity
        const bf16* hsrc = g_hbb + (size_t)(rb * 2 + d) * B_ * H_;

        // stage FULL h (64 x 512 bf16) once: 16 uint4 per thread
#pragma unroll
        for (int p = 0; p < 16; p++) {
            int idx = p * 256 + tid;
            int row = idx >> 6;
            int c8  = (idx & 63) * 8;
            *(uint4*)&h_s[row * 520 + c8] = *(const uint4*)(hsrc + (size_t)row * H_ + c8);
        }
        __syncthreads();

        float z[2][4] = {{0.f,0.f,0.f,0.f},{0.f,0.f,0.f,0.f}};
#pragma unroll 8
        for (int ks = 0; ks < 32; ks++) {
            const int kk = ks * 16 + 2 * tig;
            const int ar = wm + gid;
            uint32_t a0 = *(const uint32_t*)&whh_s[ar * 520 + kk];
            uint32_t a1 = *(const uint32_t*)&whh_s[(ar + 8) * 520 + kk];
            uint32_t a2 = *(const uint32_t*)&whh_s[ar * 520 + kk + 8];
            uint32_t a3 = *(const uint32_t*)&whh_s[(ar + 8) * 520 + kk + 8];
#pragma unroll
            for (int nt = 0; nt < 2; nt++) {
                int nc = wn + nt * 8 + gid;
                uint32_t b0 = *(const uint32_t*)&h_s[nc * 520 + kk];
                uint32_t b1 = *(const uint32_t*)&h_s[nc * 520 + kk + 8];
                mma_bf(z[nt], a0, a1, a2, a3, b0, b1);
            }
        }

        // z fragments -> smem
#pragma unroll
        for (int nt = 0; nt < 2; nt++) {
            int cc = wn + nt * 8 + tig * 2;
            *(float2*)&z_s[(wm + gid) * 68 + cc]     = make_float2(z[nt][0], z[nt][1]);
            *(float2*)&z_s[(wm + gid + 8) * 68 + cc] = make_float2(z[nt][2], z[nt][3]);
        }
        __syncthreads();

        // gates + state update for cells (jbase+j0, b), (jbase+j0+1, b)
        float hv[2];
#pragma unroll
        for (int u = 0; u < 2; u++) {
            int j = j0 + u;
            float zi = z_s[(j)      * 68 + b] + xv[0][u];
            float zf = z_s[(8 + j)  * 68 + b] + xv[1][u];
            float zg = z_s[(16 + j) * 68 + b] + xv[2][u];
            float zo = z_s[(24 + j) * 68 + b] + xv[3][u];
            float iv = sigf(zi), fv = sigf(zf), ov = sigf(zo);
            float gv = tanhf(zg);
            cst[u] = fv * cst[u] + iv * gv;
            hv[u] = ov * tanhf(cst[u]);
        }
        __nv_bfloat162 hb = __floats2bfloat162_rn(hv[0], hv[1]);
        *(__nv_bfloat162*)(g_hbb + ((size_t)(wb * 2 + d) * B_ + b) * H_ + jbase + j0) = hb;
        *(__nv_bfloat162*)(Xout + ((size_t)t * B_ + b) * (2 * H_) + d * H_ + jbase + j0) = hb;

        // split-phase barrier: overlap next step's xp loads with the chain
        gbar_arrive(d, bid, gen);
        if (s + 1 < T_) xp_prefetch(s + 1);
        gbar_wait(d, leader, gen);
        gen++;
    }
}

// ---------------- emission scores (round-8 verbatim) ----------------
__global__ __launch_bounds__(256) void feats_k(const float* __restrict__ lw,
                                               const float* __restrict__ lb)
{
    __shared__ float xs[8][129];
    __shared__ float ws[32][129];
    const int tid = threadIdx.x;
    const int r = tid >> 5, k = tid & 31;
    const size_t tb0 = (size_t)blockIdx.x * 8;
    float acc = 0.f;
    for (int c0 = 0; c0 < 2 * H_; c0 += 128) {
        for (int i = tid; i < 8 * 128; i += 256)
            xs[i >> 7][i & 127] =
                __bfloat162float(g_x2b[(tb0 + (i >> 7)) * (2 * H_) + c0 + (i & 127)]);
        for (int i = tid; i < 32 * 128; i += 256)
            ws[i >> 7][i & 127] = lw[(size_t)(i >> 7) * (2 * H_) + c0 + (i & 127)];
        __syncthreads();
#pragma unroll 16
        for (int kk = 0; kk < 128; kk++) acc += xs[r][kk] * ws[k][kk];
        __syncthreads();
    }
    g_feats[(tb0 + r) * KT + k] = acc + lb[k];
}

// ---------------- CRF (round-1 verbatim) ----------------
__global__ void crf_k(const int* __restrict__ tokens, const int* __restrict__ tags,
                      const int* __restrict__ lengths, const float* __restrict__ trans)
{
    const int b = blockIdx.x;
    const int k = threadIdx.x;              // 0..31
    __shared__ float al[KT];

    float tr[KT];
#pragma unroll
    for (int j = 0; j < KT; j++) tr[j] = trans[k * KT + j];

    al[k] = (k == 30) ? 0.f : NEGV;
    __syncwarp();

    for (int t = 0; t < T_; t++) {
        float m = -3.4e38f;
#pragma unroll
        for (int j = 0; j < KT; j++) m = fmaxf(m, al[j] + tr[j]);
        float ss = 0.f;
#pragma unroll
        for (int j = 0; j < KT; j++) ss += __expf(al[j] + tr[j] - m);
        float nw = m + __logf(ss) + g_feats[((size_t)t * B_ + b) * KT + k];
        int msk = tokens[t * B_ + b] > 0;
        __syncwarp();
        if (msk) al[k] = nw;
        __syncwarp();
    }

    float v = al[k] + trans[31 * KT + k];
    float m = v;
#pragma unroll
    for (int o = 16; o; o >>= 1) m = fmaxf(m, __shfl_xor_sync(0xffffffffu, m, o));
    float e = __expf(v - m);
#pragma unroll
    for (int o = 16; o; o >>= 1) e += __shfl_xor_sync(0xffffffffu, e, o);
    float logz = m + __logf(e);

    float gl = 0.f;
    for (int t = k; t < T_; t += 32) {
        int cur  = tags[t * B_ + b];
        int prev = (t == 0) ? 30 : tags[(t - 1) * B_ + b];
        float mm = (tokens[t * B_ + b] > 0) ? 1.f : 0.f;
        gl += mm * (trans[cur * KT + prev] + g_feats[((size_t)t * B_ + b) * KT + cur]);
    }
#pragma unroll
    for (int o = 16; o; o >>= 1) gl += __shfl_xor_sync(0xffffffffu, gl, o);
    gl += trans[31 * KT + tags[(T_ - 1) * B_ + b]];

    if (k == 0) g_part[b] = (logz - gl) / (float)lengths[b];
}

__global__ void out_k(float* __restrict__ out) {
    __shared__ float s[B_];
    s[threadIdx.x] = g_part[threadIdx.x];
    __syncthreads();
    for (int o = 32; o; o >>= 1) {
        if (threadIdx.x < o) s[threadIdx.x] += s[threadIdx.x + o];
        __syncthreads();
    }
    if (threadIdx.x == 0) out[0] = s[0];
}

// ---------------- launcher ----------------
extern "C" void kernel_launch(void* const* d_in, const int* in_sizes, int n_in,
                              void* d_out, int out_size)
{
    const int*   tokens  = (const int*)d_in[0];
    const int*   tags    = (const int*)d_in[1];
    const int*   lengths = (const int*)d_in[2];
    const float* embed   = (const float*)d_in[3];
    const float* wih0    = (const float*)d_in[4];
    const float* whh0    = (const float*)d_in[5];
    const float* b0      = (const float*)d_in[6];
    const float* wih1    = (const float*)d_in[7];
    const float* whh1    = (const float*)d_in[8];
    const float* b1      = (const float*)d_in[9];
    const float* lin_w   = (const float*)d_in[10];
    const float* lin_b   = (const float*)d_in[11];
    const float* trans   = (const float*)d_in[12];
    float* out = (float*)d_out;

    cudaFuncSetAttribute(lstm_rec_k<0>, cudaFuncAttributeMaxDynamicSharedMemorySize, REC_SMEM);
    cudaFuncSetAttribute(lstm_rec_k<1>, cudaFuncAttributeMaxDynamicSharedMemorySize, REC_SMEM);

    cvt_k<<<6144, 256>>>(wih0, wih1);

    const int n4 = T_ * B_ * E_ / 4;
    embed_k<<<(n4 + 255) / 256, 256>>>(tokens, embed);

    gemm_xp_k<0><<<dim3(16, 256, 2), 256>>>(b0);
    lstm_rec_k<0><<<128, 256, REC_SMEM>>>(whh0);

    gemm_xp_k<1><<<dim3(16, 256, 2), 256>>>(b1);
    lstm_rec_k<1><<<128, 256, REC_SMEM>>>(whh1);

    feats_k<<<T_ * B_ / 8, 256>>>(lin_w, lin_b);
    crf_k<<<B_, 32>>>(tokens, tags, lengths, trans);
    out_k<<<1, B_>>>(out);
}

// round 17
// speedup vs baseline: 1.6067x; 1.0160x over previous
#include <cuda_runtime.h>
#include <cuda_bf16.h>
#include <cstdint>

#define T_  256
#define B_  64
#define E_  512
#define H_  512
#define KT  32      // num tags
#define G4  2048    // 4*H
#define NEGV -100000.0f

typedef __nv_bfloat16 bf16;

// ---------------- scratch (static device allocations are allowed) ----------------
__device__ __align__(16) bf16 g_x0b[(size_t)T_*B_*E_];    // embedded input bf16 [tb][512]
__device__ __align__(16) bf16 g_x1b[(size_t)T_*B_*2*H_];  // layer0 out bf16 [tb][1024]
__device__ __align__(16) bf16 g_x2b[(size_t)T_*B_*2*H_];  // layer1 out bf16 [tb][1024]
__device__ __align__(16) bf16 g_wih0b[(size_t)2*G4*E_];   // wih0 bf16
__device__ __align__(16) bf16 g_wih1b[(size_t)2*G4*2*H_]; // wih1 bf16
__device__ float g_xp[(size_t)2*T_*G4*B_];        // input-proj gates fp32 [d][t][g][b]
__device__ __align__(16) bf16 g_hbb[(size_t)2*2*B_*H_];  // h bf16, ping-pong: [par][d][b][k]
__device__ float g_feats[(size_t)T_*B_*KT];       // emission scores
__device__ float g_part[B_];
__device__ __align__(256) unsigned g_flag[2][64]; // per-block arrival flags (monotonic)
__device__ unsigned g_bar_gen[2];                 // published generation (monotonic)

// ---------------- helpers ----------------
__device__ __forceinline__ void mma_bf(float* c, uint32_t a0, uint32_t a1,
                                       uint32_t a2, uint32_t a3,
                                       uint32_t b0, uint32_t b1)
{
    asm volatile(
        "mma.sync.aligned.m16n8k16.row.col.f32.bf16.bf16.f32 "
        "{%0,%1,%2,%3},{%4,%5,%6,%7},{%8,%9},{%0,%1,%2,%3};"
        : "+f"(c[0]), "+f"(c[1]), "+f"(c[2]), "+f"(c[3])
        : "r"(a0), "r"(a1), "r"(a2), "r"(a3), "r"(b0), "r"(b1));
}

__device__ __forceinline__ float sigf(float x) {
    return 1.f / (1.f + __expf(-x));
}

// grid barrier among the 64 blocks of one direction (round-12 PROVEN version).
// Arrival = plain store of a monotonic generation to the block's own flag slot;
// the leader block (sole reader of the flag lines) polls all 64 flags with 64
// threads, then publishes the generation; followers poll the generation word.
__device__ __forceinline__ void gbarrier(int d, int bid, bool leader, unsigned gen) {
    __syncthreads();
    if (leader) {
        if (threadIdx.x == 0) {
            __threadfence();
            *((volatile unsigned*)&g_flag[d][bid]) = gen;
        }
        if (threadIdx.x < 64) {
            while (*((volatile unsigned*)&g_flag[d][threadIdx.x]) < gen) { __nanosleep(8); }
        }
        __syncthreads();
        if (threadIdx.x == 0) {
            *((volatile unsigned*)&g_bar_gen[d]) = gen;
            __threadfence();
        }
    } else if (threadIdx.x == 0) {
        __threadfence();
        *((volatile unsigned*)&g_flag[d][bid]) = gen;
        while (*((volatile unsigned*)&g_bar_gen[d]) < gen) { __nanosleep(16); }
        __threadfence();
    }
    __syncthreads();
}

// ---------------- weight conversion fp32 -> bf16 (wih only) ----------------
__global__ void cvt_k(const float* __restrict__ wih0, const float* __restrict__ wih1) {
    int i = blockIdx.x * 256 + threadIdx.x;   // float4 index
    const float* s; bf16* dst; int off;
    if (i < 524288)       { s = wih0; dst = g_wih0b; off = i; }
    else if (i < 1572864) { s = wih1; dst = g_wih1b; off = i - 524288; }
    else return;
    float4 v = ((const float4*)s)[off];
    __nv_bfloat162* o = (__nv_bfloat162*)dst + (size_t)off * 2;
    o[0] = __floats2bfloat162_rn(v.x, v.y);
    o[1] = __floats2bfloat162_rn(v.z, v.w);
}

// ---------------- embedding lookup -> bf16 ----------------
__global__ void embed_k(const int* __restrict__ tokens, const float* __restrict__ embed) {
    size_t i = (size_t)blockIdx.x * blockDim.x + threadIdx.x;   // float4 index
    if (i >= (size_t)T_ * B_ * E_ / 4) return;
    size_t el = i * 4;
    size_t tb = el / E_;
    int    e  = (int)(el % E_);
    const float4 v = *(const float4*)(embed + (size_t)tokens[tb] * E_ + e);
    __nv_bfloat162* o = (__nv_bfloat162*)(g_x0b + el);
    o[0] = __floats2bfloat162_rn(v.x, v.y);
    o[1] = __floats2bfloat162_rn(v.z, v.w);
}

// ---------------- input projection GEMM: double-buffered smem, 1 sync/chunk -----
// Iteration c: LDG(c+1)->regs (hides under mma), mma reads buf[c&1],
// STS regs -> buf[(c+1)&1] (disjoint), ONE __syncthreads per chunk.
template<int L>
__global__ __launch_bounds__(256) void gemm_xp_k(const float* __restrict__ bias)
{
    constexpr int KSZ = (L == 0) ? 512 : 1024;
    constexpr int NC  = KSZ / 32;
    const bf16* X = (L == 0) ? g_x0b : g_x1b;
    const bf16* Wb = (L == 0) ? g_wih0b : g_wih1b;

    __shared__ __align__(16) bf16 As[2][128 * 40];
    __shared__ __align__(16) bf16 Bs[2][64 * 40];

    const int d = blockIdx.z, t = blockIdx.y, gbase = blockIdx.x * 128;
    const bf16* Wd = Wb + (size_t)d * G4 * KSZ;
    const bf16* Xt = X + (size_t)t * B_ * KSZ;

    const int tid = threadIdx.x, warp = tid >> 5, lane = tid & 31;
    const int wm = (warp >> 1) * 32, wn = (warp & 1) * 32;
    const int gid = lane >> 2, tig = lane & 3;

    float acc[2][4][4];
#pragma unroll
    for (int a = 0; a < 2; a++)
#pragma unroll
        for (int b = 0; b < 4; b++)
#pragma unroll
            for (int c = 0; c < 4; c++) acc[a][b][c] = 0.f;

    const int row0 = tid >> 2;          // 0..63
    const int c8   = (tid & 3) * 8;

    uint4 ra0, ra1, rbv;
    auto LD = [&](int c) {
        const int k0 = c * 32;
        ra0 = *(const uint4*)(Wd + (size_t)(gbase + row0) * KSZ + k0 + c8);
        ra1 = *(const uint4*)(Wd + (size_t)(gbase + row0 + 64) * KSZ + k0 + c8);
        rbv = *(const uint4*)(Xt + (size_t)row0 * KSZ + k0 + c8);
    };
    auto STS = [&](int buf) {
        *(uint4*)&As[buf][row0 * 40 + c8]        = ra0;
        *(uint4*)&As[buf][(row0 + 64) * 40 + c8] = ra1;
        *(uint4*)&Bs[buf][row0 * 40 + c8]        = rbv;
    };

    LD(0);
    STS(0);
    __syncthreads();

    for (int c = 0; c < NC; c++) {
        if (c + 1 < NC) LD(c + 1);          // LDG hides under this chunk's mma
        const bf16* A  = As[c & 1];
        const bf16* Bm = Bs[c & 1];
#pragma unroll
        for (int ks = 0; ks < 2; ks++) {
            const int kk = ks * 16 + 2 * tig;
            uint32_t a[2][4];
#pragma unroll
            for (int mt = 0; mt < 2; mt++) {
                const bf16* ap = A + (wm + mt * 16 + gid) * 40;
                a[mt][0] = *(const uint32_t*)(ap + kk);
                a[mt][1] = *(const uint32_t*)(ap + 8 * 40 + kk);
                a[mt][2] = *(const uint32_t*)(ap + kk + 8);
                a[mt][3] = *(const uint32_t*)(ap + 8 * 40 + kk + 8);
            }
#pragma unroll
            for (int nt = 0; nt < 4; nt++) {
                const bf16* bp = Bm + (wn + nt * 8 + gid) * 40;
                uint32_t b0 = *(const uint32_t*)(bp + kk);
                uint32_t b1 = *(const uint32_t*)(bp + kk + 8);
                mma_bf(acc[0][nt], a[0][0], a[0][1], a[0][2], a[0][3], b0, b1);
                mma_bf(acc[1][nt], a[1][0], a[1][1], a[1][2], a[1][3], b0, b1);
            }
        }
        if (c + 1 < NC) STS((c + 1) & 1);   // disjoint buffer: no hazard with mma(c)
        __syncthreads();
    }

    float* XP = g_xp + ((size_t)(d * T_ + t) * G4) * B_;
#pragma unroll
    for (int mt = 0; mt < 2; mt++) {
        int r0 = gbase + wm + mt * 16 + gid;
        float bb0 = bias[(size_t)d * G4 + r0];
        float bb1 = bias[(size_t)d * G4 + r0 + 8];
#pragma unroll
        for (int nt = 0; nt < 4; nt++) {
            int c = wn + nt * 8 + tig * 2;
            float2 v0 = make_float2(acc[mt][nt][0] + bb0, acc[mt][nt][1] + bb0);
            float2 v1 = make_float2(acc[mt][nt][2] + bb1, acc[mt][nt][3] + bb1);
            *(float2*)(XP + (size_t)r0 * B_ + c)       = v0;
            *(float2*)(XP + (size_t)(r0 + 8) * B_ + c) = v1;
        }
    }
}

// ---------------- recurrence kernel (round-12 VERBATIM) --------------------------
// smem: whh 32x520 bf16 + h 64x520 bf16 + z 32x68 f32 = 108544 B
#define REC_SMEM ((32 * 520 + 64 * 520) * 2 + 32 * 68 * 4)

template<int L>
__global__ __launch_bounds__(256, 1) void lstm_rec_k(const float* __restrict__ Whh)
{
    bf16* Xout = (L == 0) ? g_x1b : g_x2b;
    extern __shared__ char smraw[];
    bf16*  whh_s = (bf16*)smraw;                     // [32][520]
    bf16*  h_s   = (bf16*)(smraw + 32 * 520 * 2);    // [64][520]
    float* z_s   = (float*)(smraw + (32 + 64) * 520 * 2); // [32][68]

    const int blk = blockIdx.x;
    const int d = blk >> 6;
    const int bid = blk & 63;
    const int jbase = bid * 8;
    const bool leader = bid == 0;
    const int tid = threadIdx.x, warp = tid >> 5, lane = tid & 31;
    const int gid = lane >> 2, tig = lane & 3;
    const int wm = (warp >> 2) * 16, wn = (warp & 3) * 16;

    // read generation base (stable at kernel entry; monotonic across replays)
    __shared__ unsigned s_base;
    if (tid == 0) s_base = *((volatile unsigned*)&g_bar_gen[d]);

    const float* Wd = Whh + (size_t)d * G4 * H_;

    // load + convert this block's 32 Whh rows (local m = q*8+jl <-> q*512+jbase+jl)
    for (int i = tid; i < 32 * 128; i += 256) {
        int m = i >> 7, c4 = (i & 127) * 4;
        int grow = (m >> 3) * 512 + jbase + (m & 7);
        float4 v = *(const float4*)(Wd + (size_t)grow * H_ + c4);
        __nv_bfloat162 p0 = __floats2bfloat162_rn(v.x, v.y);
        __nv_bfloat162 p1 = __floats2bfloat162_rn(v.z, v.w);
        uint2 pk = make_uint2(*(uint32_t*)&p0, *(uint32_t*)&p1);
        *(uint2*)&whh_s[m * 520 + c4] = pk;
    }

    // per-thread cells: b = tid>>2 (0..63), j0 = (tid&3)*2
    const int b  = tid >> 2;
    const int j0 = (tid & 3) * 2;
    float cst[2] = {0.f, 0.f};

    // zero h_{-1} into parity buffer 0
    *(__nv_bfloat162*)(g_hbb + ((size_t)(0 * 2 + d) * B_ + b) * H_ + jbase + j0) =
        __floats2bfloat162_rn(0.f, 0.f);

    __syncthreads();
    unsigned gen = s_base + 1;

    gbarrier(d, bid, leader, gen); gen++;

    for (int s = 0; s < T_; s++) {
        const int t = (d == 0) ? s : (T_ - 1 - s);
        const int rb = s & 1;          // read parity
        const int wb = rb ^ 1;         // write parity
        const bf16* hsrc = g_hbb + (size_t)(rb * 2 + d) * B_ * H_;

        // hoisted xp gate loads (8 independent fp32; hide under staging + mma)
        const float* xpb = g_xp + ((size_t)(d * T_ + t) * G4 + jbase) * B_;
        float xv[4][2];
#pragma unroll
        for (int q = 0; q < 4; q++)
#pragma unroll
            for (int u = 0; u < 2; u++)
                xv[q][u] = xpb[(size_t)(q * 512 + j0 + u) * B_ + b];

        // stage FULL h (64 x 512 bf16) once: 16 uint4 per thread
#pragma unroll
        for (int p = 0; p < 16; p++) {
            int idx = p * 256 + tid;
            int row = idx >> 6;
            int c8  = (idx & 63) * 8;
            *(uint4*)&h_s[row * 520 + c8] = *(const uint4*)(hsrc + (size_t)row * H_ + c8);
        }
        __syncthreads();

        float z[2][4] = {{0.f,0.f,0.f,0.f},{0.f,0.f,0.f,0.f}};
#pragma unroll 8
        for (int ks = 0; ks < 32; ks++) {
            const int kk = ks * 16 + 2 * tig;
            const int ar = wm + gid;
            uint32_t a0 = *(const uint32_t*)&whh_s[ar * 520 + kk];
            uint32_t a1 = *(const uint32_t*)&whh_s[(ar + 8) * 520 + kk];
            uint32_t a2 = *(const uint32_t*)&whh_s[ar * 520 + kk + 8];
            uint32_t a3 = *(const uint32_t*)&whh_s[(ar + 8) * 520 + kk + 8];
#pragma unroll
            for (int nt = 0; nt < 2; nt++) {
                int nc = wn + nt * 8 + gid;
                uint32_t b0 = *(const uint32_t*)&h_s[nc * 520 + kk];
                uint32_t b1 = *(const uint32_t*)&h_s[nc * 520 + kk + 8];
                mma_bf(z[nt], a0, a1, a2, a3, b0, b1);
            }
        }

        // z fragments -> smem
#pragma unroll
        for (int nt = 0; nt < 2; nt++) {
            int cc = wn + nt * 8 + tig * 2;
            *(float2*)&z_s[(wm + gid) * 68 + cc]     = make_float2(z[nt][0], z[nt][1]);
            *(float2*)&z_s[(wm + gid + 8) * 68 + cc] = make_float2(z[nt][2], z[nt][3]);
        }
        __syncthreads();

        // gates + state update for cells (jbase+j0, b), (jbase+j0+1, b)
        float hv[2];
#pragma unroll
        for (int u = 0; u < 2; u++) {
            int j = j0 + u;
            float zi = z_s[(j)      * 68 + b] + xv[0][u];
            float zf = z_s[(8 + j)  * 68 + b] + xv[1][u];
            float zg = z_s[(16 + j) * 68 + b] + xv[2][u];
            float zo = z_s[(24 + j) * 68 + b] + xv[3][u];
            float iv = sigf(zi), fv = sigf(zf), ov = sigf(zo);
            float gv = tanhf(zg);
            cst[u] = fv * cst[u] + iv * gv;
            hv[u] = ov * tanhf(cst[u]);
        }
        __nv_bfloat162 hb = __floats2bfloat162_rn(hv[0], hv[1]);
        *(__nv_bfloat162*)(g_hbb + ((size_t)(wb * 2 + d) * B_ + b) * H_ + jbase + j0) = hb;
        *(__nv_bfloat162*)(Xout + ((size_t)t * B_ + b) * (2 * H_) + d * H_ + jbase + j0) = hb;

        gbarrier(d, bid, leader, gen); gen++;
    }
}

// ---------------- emission scores (round-8 verbatim) ----------------
__global__ __launch_bounds__(256) void feats_k(const float* __restrict__ lw,
                                               const float* __restrict__ lb)
{
    __shared__ float xs[8][129];
    __shared__ float ws[32][129];
    const int tid = threadIdx.x;
    const int r = tid >> 5, k = tid & 31;
    const size_t tb0 = (size_t)blockIdx.x * 8;
    float acc = 0.f;
    for (int c0 = 0; c0 < 2 * H_; c0 += 128) {
        for (int i = tid; i < 8 * 128; i += 256)
            xs[i >> 7][i & 127] =
                __bfloat162float(g_x2b[(tb0 + (i >> 7)) * (2 * H_) + c0 + (i & 127)]);
        for (int i = tid; i < 32 * 128; i += 256)
            ws[i >> 7][i & 127] = lw[(size_t)(i >> 7) * (2 * H_) + c0 + (i & 127)];
        __syncthreads();
#pragma unroll 16
        for (int kk = 0; kk < 128; kk++) acc += xs[r][kk] * ws[k][kk];
        __syncthreads();
    }
    g_feats[(tb0 + r) * KT + k] = acc + lb[k];
}

// ---------------- CRF (round-1 verbatim) ----------------
__global__ void crf_k(const int* __restrict__ tokens, const int* __restrict__ tags,
                      const int* __restrict__ lengths, const float* __restrict__ trans)
{
    const int b = blockIdx.x;
    const int k = threadIdx.x;              // 0..31
    __shared__ float al[KT];

    float tr[KT];
#pragma unroll
    for (int j = 0; j < KT; j++) tr[j] = trans[k * KT + j];

    al[k] = (k == 30) ? 0.f : NEGV;
    __syncwarp();

    for (int t = 0; t < T_; t++) {
        float m = -3.4e38f;
#pragma unroll
        for (int j = 0; j < KT; j++) m = fmaxf(m, al[j] + tr[j]);
        float ss = 0.f;
#pragma unroll
        for (int j = 0; j < KT; j++) ss += __expf(al[j] + tr[j] - m);
        float nw = m + __logf(ss) + g_feats[((size_t)t * B_ + b) * KT + k];
        int msk = tokens[t * B_ + b] > 0;
        __syncwarp();
        if (msk) al[k] = nw;
        __syncwarp();
    }

    float v = al[k] + trans[31 * KT + k];
    float m = v;
#pragma unroll
    for (int o = 16; o; o >>= 1) m = fmaxf(m, __shfl_xor_sync(0xffffffffu, m, o));
    float e = __expf(v - m);
#pragma unroll
    for (int o = 16; o; o >>= 1) e += __shfl_xor_sync(0xffffffffu, e, o);
    float logz = m + __logf(e);

    float gl = 0.f;
    for (int t = k; t < T_; t += 32) {
        int cur  = tags[t * B_ + b];
        int prev = (t == 0) ? 30 : tags[(t - 1) * B_ + b];
        float mm = (tokens[t * B_ + b] > 0) ? 1.f : 0.f;
        gl += mm * (trans[cur * KT + prev] + g_feats[((size_t)t * B_ + b) * KT + cur]);
    }
#pragma unroll
    for (int o = 16; o; o >>= 1) gl += __shfl_xor_sync(0xffffffffu, gl, o);
    gl += trans[31 * KT + tags[(T_ - 1) * B_ + b]];

    if (k == 0) g_part[b] = (logz - gl) / (float)lengths[b];
}

__global__ void out_k(float* __restrict__ out) {
    __shared__ float s[B_];
    s[threadIdx.x] = g_part[threadIdx.x];
    __syncthreads();
    for (int o = 32; o; o >>= 1) {
        if (threadIdx.x < o) s[threadIdx.x] += s[threadIdx.x + o];
        __syncthreads();
    }
    if (threadIdx.x == 0) out[0] = s[0];
}

// ---------------- launcher ----------------
extern "C" void kernel_launch(void* const* d_in, const int* in_sizes, int n_in,
                              void* d_out, int out_size)
{
    const int*   tokens  = (const int*)d_in[0];
    const int*   tags    = (const int*)d_in[1];
    const int*   lengths = (const int*)d_in[2];
    const float* embed   = (const float*)d_in[3];
    const float* wih0    = (const float*)d_in[4];
    const float* whh0    = (const float*)d_in[5];
    const float* b0      = (const float*)d_in[6];
    const float* wih1    = (const float*)d_in[7];
    const float* whh1    = (const float*)d_in[8];
    const float* b1      = (const float*)d_in[9];
    const float* lin_w   = (const float*)d_in[10];
    const float* lin_b   = (const float*)d_in[11];
    const float* trans   = (const float*)d_in[12];
    float* out = (float*)d_out;

    cudaFuncSetAttribute(lstm_rec_k<0>, cudaFuncAttributeMaxDynamicSharedMemorySize, REC_SMEM);
    cudaFuncSetAttribute(lstm_rec_k<1>, cudaFuncAttributeMaxDynamicSharedMemorySize, REC_SMEM);

    cvt_k<<<6144, 256>>>(wih0, wih1);

    const int n4 = T_ * B_ * E_ / 4;
    embed_k<<<(n4 + 255) / 256, 256>>>(tokens, embed);

    gemm_xp_k<0><<<dim3(16, 256, 2), 256>>>(b0);
    lstm_rec_k<0><<<128, 256, REC_SMEM>>>(whh0);

    gemm_xp_k<1><<<dim3(16, 256, 2), 256>>>(b1);
    lstm_rec_k<1><<<128, 256, REC_SMEM>>>(whh1);

    feats_k<<<T_ * B_ / 8, 256>>>(lin_w, lin_b);
    crf_k<<<B_, 32>>>(tokens, tags, lengths, trans);
    out_k<<<1, B_>>>(out);
}